// round 6
// baseline (speedup 1.0000x reference)
#include <cuda_runtime.h>

// LIF recurrence, forward spikes only.
// x: [T=32, B, D] fp32, out: same shape, spikes in {0.0, 1.0}.
//
//   mem_t   = dec_{t-1} + x_t ; spike_t = mem_t > 0.5
//   dec_t   = spike_t ? 0 : mem_t * 0.25      (carried state, dec_{-1}=0)
//
// Touch-once HBM stream (268 MB). R2-R5: DRAM% plateaus at ~74% across all
// occ/MLP configurations -> ceiling is DRAM efficiency of 512B warp requests
// from 100k+ interleaved streams. This round: 256-bit ld/st (sm_100+ v8.f32)
// -> 1KB contiguous per warp request, half the streams, half the memory
// instructions. Never-drain ping-pong pipeline retained (chunk = 2 timesteps).

#define THRESH 0.5f
#define DECAY  0.25f

__device__ __forceinline__ void ldg256(float* d, const float* p)
{
    asm volatile(
        "ld.global.cs.v8.f32 {%0,%1,%2,%3,%4,%5,%6,%7}, [%8];"
        : "=f"(d[0]), "=f"(d[1]), "=f"(d[2]), "=f"(d[3]),
          "=f"(d[4]), "=f"(d[5]), "=f"(d[6]), "=f"(d[7])
        : "l"(p));
}

__device__ __forceinline__ void stg256(float* p, const float* s)
{
    asm volatile(
        "st.global.cs.v8.f32 [%0], {%1,%2,%3,%4,%5,%6,%7,%8};"
        :: "l"(p),
           "f"(s[0]), "f"(s[1]), "f"(s[2]), "f"(s[3]),
           "f"(s[4]), "f"(s[5]), "f"(s[6]), "f"(s[7])
        : "memory");
}

// load 2 timesteps (2 x v8) into buffer b[16]
__device__ __forceinline__ void load2(float (&b)[16], const float* __restrict__ p,
                                      long stf)   // stride in floats between timesteps
{
    ldg256(&b[0], p);
    ldg256(&b[8], p + stf);
}

// compute + store 2 timesteps from buffer
__device__ __forceinline__ void comp2(const float (&b)[16], float (&dec)[8],
                                      float* __restrict__ op, long stf)
{
    #pragma unroll
    for (int t = 0; t < 2; t++) {
        float s[8];
        #pragma unroll
        for (int j = 0; j < 8; j++) {
            float m = dec[j] + b[t * 8 + j];
            s[j]   = (m > THRESH) ? 1.0f : 0.0f;
            dec[j] = (m > THRESH) ? 0.0f : m * DECAY;
        }
        stg256(op + (long)t * stf, s);
    }
}

__global__ __launch_bounds__(128) void lif_kernel(
    const float* __restrict__ x,
    float* __restrict__ out,
    int BD)    // elements per timestep
{
    long i = (long)(blockIdx.x * blockDim.x + threadIdx.x) * 8;  // 8 floats/thread
    const long stf = BD;                    // float stride per timestep
    const float* __restrict__ xp = x + i;
    float* __restrict__       op = out + i;

    float A[16], B[16];
    float dec[8];
    #pragma unroll
    for (int j = 0; j < 8; j++) dec[j] = 0.0f;

    // 16 chunks of 2 timesteps; loads stay one chunk ahead of compute.
    load2(A, xp + 0 * 2 * stf, stf);
    load2(B, xp + 1 * 2 * stf, stf);

    #pragma unroll
    for (int c = 0; c < 16; c++) {
        if (c & 1) {
            comp2(B, dec, op + (long)c * 2 * stf, stf);
            if (c + 2 < 16) load2(B, xp + (long)(c + 2) * 2 * stf, stf);
        } else {
            comp2(A, dec, op + (long)c * 2 * stf, stf);
            if (c + 2 < 16) load2(A, xp + (long)(c + 2) * 2 * stf, stf);
        }
    }
}

extern "C" void kernel_launch(void* const* d_in, const int* in_sizes, int n_in,
                              void* d_out, int out_size)
{
    const float* x = (const float*)d_in[0];
    float* out = (float*)d_out;

    const int T = 32;
    int total = in_sizes[0];        // T * B * D
    int BD = total / T;             // 1,048,576
    int chains8 = BD / 8;           // 131,072 threads

    int threads = 128;
    int blocks = chains8 / threads; // exact: 1024
    lif_kernel<<<blocks, threads>>>(x, out, BD);
}